// round 1
// baseline (speedup 1.0000x reference)
#include <cuda_runtime.h>
#include <cuda_bf16.h>
#include <math.h>

#define DIMN 3072
#define HEADS 24
#define HD 128
#define BATCH 2
#define S_IMG 1024
#define S_TXT 512
#define SEQ 1536
#define SCALE 0.08838834764831845f   // 1/sqrt(128)

// ---------------- scratch (static device arrays; no allocation) ----------------
__device__ float g_qbuf[(size_t)BATCH * SEQ * DIMN];
__device__ float g_kbuf[(size_t)BATCH * SEQ * DIMN];
__device__ float g_vbuf[(size_t)BATCH * SEQ * DIMN];
__device__ float g_obuf[(size_t)BATCH * SEQ * DIMN];

// ---------------- SGEMM: C[row] = A[row] @ W + bias, flexible row maps ----------------
// A rows: phys_row = (r / S_part) * in_sb + in_off + (r % S_part)
// C rows: phys_row = (r / S_part) * out_sb + out_off + (r % S_part)
#define BM 128
#define BN 128
#define BK 8

__global__ __launch_bounds__(256) void sgemm_bias(
    const float* __restrict__ A, const float* __restrict__ W,
    const float* __restrict__ bias, float* __restrict__ C,
    int S_part, int in_sb, int in_off, int out_sb, int out_off)
{
    __shared__ float As[BK][BM];
    __shared__ float Bs[BK][BN];

    const int t  = threadIdx.x;           // 0..255
    const int bm = blockIdx.y * BM;
    const int bn = blockIdx.x * BN;
    const int tx = t & 15, ty = t >> 4;   // 16x16

    // A-tile load mapping: each thread loads one float4
    const int a_r = t >> 1;               // 0..127
    const int a_c = (t & 1) << 2;         // 0 or 4
    const int gr  = bm + a_r;
    const int ab  = gr / S_part, as = gr - ab * S_part;
    const float* Arow = A + (size_t)(ab * in_sb + in_off + as) * DIMN;

    // B-tile load mapping
    const int b_kr = t >> 5;              // 0..7
    const int b_cc = (t & 31) << 2;       // 0..124
    const float* Wp = W + (size_t)b_kr * DIMN + bn + b_cc;

    float acc[8][8];
    #pragma unroll
    for (int i = 0; i < 8; i++)
        #pragma unroll
        for (int j = 0; j < 8; j++) acc[i][j] = 0.f;

    for (int k0 = 0; k0 < DIMN; k0 += BK) {
        float4 av = *(const float4*)(Arow + k0 + a_c);
        As[a_c + 0][a_r] = av.x; As[a_c + 1][a_r] = av.y;
        As[a_c + 2][a_r] = av.z; As[a_c + 3][a_r] = av.w;
        float4 bv = *(const float4*)(Wp + (size_t)k0 * DIMN);
        *(float4*)&Bs[b_kr][b_cc] = bv;
        __syncthreads();
        #pragma unroll
        for (int kk = 0; kk < BK; kk++) {
            float4 a0 = *(const float4*)&As[kk][ty * 8];
            float4 a1 = *(const float4*)&As[kk][ty * 8 + 4];
            float4 b0 = *(const float4*)&Bs[kk][tx * 8];
            float4 b1 = *(const float4*)&Bs[kk][tx * 8 + 4];
            float ra[8] = {a0.x,a0.y,a0.z,a0.w,a1.x,a1.y,a1.z,a1.w};
            float rb[8] = {b0.x,b0.y,b0.z,b0.w,b1.x,b1.y,b1.z,b1.w};
            #pragma unroll
            for (int i = 0; i < 8; i++)
                #pragma unroll
                for (int j = 0; j < 8; j++)
                    acc[i][j] += ra[i] * rb[j];
        }
        __syncthreads();
    }

    #pragma unroll
    for (int i = 0; i < 8; i++) {
        int r  = bm + ty * 8 + i;
        int cb = r / S_part, cs = r - cb * S_part;
        float* Crow = C + (size_t)(cb * out_sb + out_off + cs) * DIMN + bn + tx * 8;
        #pragma unroll
        for (int j = 0; j < 8; j++)
            Crow[j] = acc[i][j] + bias[bn + tx * 8 + j];
    }
}

// ---------------- per-head RMSNorm + RoPE (in place on q/k buffers) ----------------
__global__ __launch_bounds__(128) void rmsrope_kernel(
    float* __restrict__ q, float* __restrict__ k,
    const float* __restrict__ cosb, const float* __restrict__ sinb,
    const float* __restrict__ gq, const float* __restrict__ gqc,
    const float* __restrict__ gk, const float* __restrict__ gkc)
{
    const int s = blockIdx.x;             // 0..1535
    const int b = blockIdx.y;             // 0..1
    const int h = blockIdx.z % HEADS;
    const int which = blockIdx.z / HEADS; // 0=q, 1=k
    float* buf = which ? k : q;
    const float* g = which ? (s < S_TXT ? gkc : gk) : (s < S_TXT ? gqc : gq);
    const int d = threadIdx.x;

    const size_t base = ((size_t)(b * SEQ + s)) * DIMN + h * HD;
    float v = buf[base + d];
    float ss = v * v;
    #pragma unroll
    for (int o = 16; o; o >>= 1) ss += __shfl_xor_sync(0xffffffffu, ss, o);
    __shared__ float wsum[4];
    __shared__ float nbuf[HD];
    if ((d & 31) == 0) wsum[d >> 5] = ss;
    __syncthreads();
    float tot = wsum[0] + wsum[1] + wsum[2] + wsum[3];
    float r = rsqrtf(tot * (1.0f / HD) + 1e-6f);
    nbuf[d] = v * r * g[d];
    __syncthreads();
    if (d < 64) {
        float x1 = nbuf[2 * d], x2 = nbuf[2 * d + 1];
        float c  = cosb[s * 64 + d], sn = sinb[s * 64 + d];
        buf[base + 2 * d]     = x1 * c - x2 * sn;
        buf[base + 2 * d + 1] = x1 * sn + x2 * c;
    }
}

// ---------------- flash attention, fp32, 64x64 tiles ----------------
#define KS_STRIDE 132
#define PS_STRIDE 65

__global__ __launch_bounds__(256) void attn_kernel(
    const float* __restrict__ Q, const float* __restrict__ K,
    const float* __restrict__ V, float* __restrict__ O)
{
    extern __shared__ float sm[];
    float* Qs  = sm;                                  // 64*128
    float* Ks  = Qs + 64 * 128;                       // 64*132
    float* Vs  = Ks + 64 * KS_STRIDE;                 // 64*132
    float* Ps  = Vs + 64 * KS_STRIDE;                 // 64*65
    float* m_s = Ps + 64 * PS_STRIDE;                 // 64
    float* l_s = m_s + 64;                            // 64
    float* sc_s = l_s + 64;                           // 64

    const int t  = threadIdx.x;
    const int m0 = blockIdx.x * 64;
    const int h  = blockIdx.y;
    const int b  = blockIdx.z;
    const size_t seqbase = (size_t)b * SEQ;
    const int tx = t & 15, ty = t >> 4;

    // stage Q (pre-scaled)
    const float* Qg = Q + (seqbase + m0) * DIMN + h * HD;
    for (int i = t; i < 64 * 32; i += 256) {
        int r = i >> 5, c4 = (i & 31) << 2;
        float4 v = *(const float4*)(Qg + (size_t)r * DIMN + c4);
        v.x *= SCALE; v.y *= SCALE; v.z *= SCALE; v.w *= SCALE;
        *(float4*)(Qs + r * 128 + c4) = v;
    }
    if (t < 64) { m_s[t] = -1e30f; l_s[t] = 0.f; }
    float o[4][8];
    #pragma unroll
    for (int i = 0; i < 4; i++)
        #pragma unroll
        for (int j = 0; j < 8; j++) o[i][j] = 0.f;
    __syncthreads();

    for (int n0 = 0; n0 < SEQ; n0 += 64) {
        const float* Kg = K + (seqbase + n0) * DIMN + h * HD;
        const float* Vg = V + (seqbase + n0) * DIMN + h * HD;
        for (int i = t; i < 8192; i += 256) {
            int r = i >> 7, d = i & 127;
            Ks[r * KS_STRIDE + d] = Kg[(size_t)r * DIMN + d];
            Vs[r * KS_STRIDE + d] = Vg[(size_t)r * DIMN + d];
        }
        __syncthreads();

        // scores S = Q K^T  (thread: rows ty+16i, cols tx+16j)
        float s4[4][4];
        #pragma unroll
        for (int i = 0; i < 4; i++)
            #pragma unroll
            for (int j = 0; j < 4; j++) s4[i][j] = 0.f;
        for (int d = 0; d < 128; d += 4) {
            float4 qa[4], kb[4];
            #pragma unroll
            for (int i = 0; i < 4; i++)
                qa[i] = *(const float4*)(Qs + (ty + 16 * i) * 128 + d);
            #pragma unroll
            for (int j = 0; j < 4; j++)
                kb[j] = *(const float4*)(Ks + (tx + 16 * j) * KS_STRIDE + d);
            #pragma unroll
            for (int i = 0; i < 4; i++)
                #pragma unroll
                for (int j = 0; j < 4; j++)
                    s4[i][j] += qa[i].x * kb[j].x + qa[i].y * kb[j].y
                              + qa[i].z * kb[j].z + qa[i].w * kb[j].w;
        }
        #pragma unroll
        for (int i = 0; i < 4; i++)
            #pragma unroll
            for (int j = 0; j < 4; j++)
                Ps[(ty + 16 * i) * PS_STRIDE + tx + 16 * j] = s4[i][j];
        __syncthreads();

        // online softmax: 4 threads per row
        {
            int r = t >> 2, p = t & 3;
            float* prow = Ps + r * PS_STRIDE + p * 16;
            float mx = prow[0];
            #pragma unroll
            for (int c = 1; c < 16; c++) mx = fmaxf(mx, prow[c]);
            mx = fmaxf(mx, __shfl_xor_sync(0xffffffffu, mx, 1));
            mx = fmaxf(mx, __shfl_xor_sync(0xffffffffu, mx, 2));
            float m_old = m_s[r];
            float m_new = fmaxf(m_old, mx);
            float sum = 0.f;
            #pragma unroll
            for (int c = 0; c < 16; c++) {
                float e = __expf(prow[c] - m_new);
                prow[c] = e;
                sum += e;
            }
            sum += __shfl_xor_sync(0xffffffffu, sum, 1);
            sum += __shfl_xor_sync(0xffffffffu, sum, 2);
            if (p == 0) {
                float scale = __expf(m_old - m_new);
                l_s[r] = l_s[r] * scale + sum;
                m_s[r] = m_new;
                sc_s[r] = scale;
            }
        }
        __syncthreads();

        // rescale + O += P V   (thread: rows ty+16i, cols tx+16j, j<8)
        #pragma unroll
        for (int i = 0; i < 4; i++) {
            float sc = sc_s[ty + 16 * i];
            #pragma unroll
            for (int j = 0; j < 8; j++) o[i][j] *= sc;
        }
        for (int kk = 0; kk < 64; kk++) {
            float pv[4], vv[8];
            #pragma unroll
            for (int i = 0; i < 4; i++) pv[i] = Ps[(ty + 16 * i) * PS_STRIDE + kk];
            #pragma unroll
            for (int j = 0; j < 8; j++) vv[j] = Vs[kk * KS_STRIDE + tx + 16 * j];
            #pragma unroll
            for (int i = 0; i < 4; i++)
                #pragma unroll
                for (int j = 0; j < 8; j++)
                    o[i][j] += pv[i] * vv[j];
        }
        __syncthreads();
    }

    float* Og = O + (seqbase + m0) * DIMN + h * HD;
    #pragma unroll
    for (int i = 0; i < 4; i++) {
        float inv = 1.f / l_s[ty + 16 * i];
        #pragma unroll
        for (int j = 0; j < 8; j++)
            Og[(size_t)(ty + 16 * i) * DIMN + tx + 16 * j] = o[i][j] * inv;
    }
}

// ---------------- launch ----------------
extern "C" void kernel_launch(void* const* d_in, const int* in_sizes, int n_in,
                              void* d_out, int out_size)
{
    const float* x        = (const float*)d_in[0];
    const float* ctx      = (const float*)d_in[1];
    const float* rope_cos = (const float*)d_in[2];
    const float* rope_sin = (const float*)d_in[3];
    const float* wq   = (const float*)d_in[4];
    const float* bq   = (const float*)d_in[5];
    const float* wk   = (const float*)d_in[6];
    const float* bk   = (const float*)d_in[7];
    const float* wv   = (const float*)d_in[8];
    const float* bv   = (const float*)d_in[9];
    const float* wqc  = (const float*)d_in[10];
    const float* bqc  = (const float*)d_in[11];
    const float* wkc  = (const float*)d_in[12];
    const float* bkc  = (const float*)d_in[13];
    const float* wvc  = (const float*)d_in[14];
    const float* bvc  = (const float*)d_in[15];
    const float* w_out     = (const float*)d_in[16];
    const float* b_out     = (const float*)d_in[17];
    const float* w_add_out = (const float*)d_in[18];
    const float* b_add_out = (const float*)d_in[19];
    const float* g_q  = (const float*)d_in[20];
    const float* g_k  = (const float*)d_in[21];
    const float* g_qc = (const float*)d_in[22];
    const float* g_kc = (const float*)d_in[23];
    float* out = (float*)d_out;

    float *qb, *kb, *vb, *ob;
    cudaGetSymbolAddress((void**)&qb, g_qbuf);
    cudaGetSymbolAddress((void**)&kb, g_kbuf);
    cudaGetSymbolAddress((void**)&vb, g_vbuf);
    cudaGetSymbolAddress((void**)&ob, g_obuf);

    const int smem_attn = (64 * 128 + 2 * 64 * KS_STRIDE + 64 * PS_STRIDE + 3 * 64) * 4;
    cudaFuncSetAttribute(attn_kernel, cudaFuncAttributeMaxDynamicSharedMemorySize, smem_attn);

    dim3 blk(256);
    // QKV projections: ctx part (joint seq rows 0..511), img part (rows 512..1535)
    dim3 grid_ctx(DIMN / BN, (BATCH * S_TXT) / BM);
    dim3 grid_img(DIMN / BN, (BATCH * S_IMG) / BM);
    sgemm_bias<<<grid_ctx, blk>>>(ctx, wqc, bqc, qb, S_TXT, S_TXT, 0, SEQ, 0);
    sgemm_bias<<<grid_ctx, blk>>>(ctx, wkc, bkc, kb, S_TXT, S_TXT, 0, SEQ, 0);
    sgemm_bias<<<grid_ctx, blk>>>(ctx, wvc, bvc, vb, S_TXT, S_TXT, 0, SEQ, 0);
    sgemm_bias<<<grid_img, blk>>>(x,   wq,  bq,  qb, S_IMG, S_IMG, 0, SEQ, S_TXT);
    sgemm_bias<<<grid_img, blk>>>(x,   wk,  bk,  kb, S_IMG, S_IMG, 0, SEQ, S_TXT);
    sgemm_bias<<<grid_img, blk>>>(x,   wv,  bv,  vb, S_IMG, S_IMG, 0, SEQ, S_TXT);

    // RMSNorm + RoPE on q,k (in place)
    dim3 grid_rr(SEQ, BATCH, 2 * HEADS);
    rmsrope_kernel<<<grid_rr, 128>>>(qb, kb, rope_cos, rope_sin, g_q, g_qc, g_k, g_kc);

    // attention
    dim3 grid_at(SEQ / 64, HEADS, BATCH);
    attn_kernel<<<grid_at, blk, smem_attn>>>(qb, kb, vb, ob);

    // output projections: txt rows -> out[0:], img rows -> out[B*S_TXT*DIM:]
    sgemm_bias<<<grid_ctx, blk>>>(ob, w_add_out, b_add_out, out,
                                  S_TXT, SEQ, 0, S_TXT, 0);
    sgemm_bias<<<grid_img, blk>>>(ob, w_out, b_out, out + (size_t)BATCH * S_TXT * DIMN,
                                  S_IMG, SEQ, S_TXT, S_IMG, 0);
}

// round 2
// speedup vs baseline: 2.0437x; 2.0437x over previous
#include <cuda_runtime.h>
#include <cuda_bf16.h>
#include <math.h>

#define DIMN 3072
#define HEADS 24
#define HD 128
#define BATCH 2
#define S_IMG 1024
#define S_TXT 512
#define SEQ 1536
#define SCALE 0.08838834764831845f   // 1/sqrt(128)

// ---------------- scratch ----------------
__device__ float g_qbuf[(size_t)BATCH * SEQ * DIMN];
__device__ float g_kbuf[(size_t)BATCH * SEQ * DIMN];
__device__ float g_vbuf[(size_t)BATCH * SEQ * DIMN];
__device__ float g_obuf[(size_t)BATCH * SEQ * DIMN];

__device__ __forceinline__ unsigned f2tf(float f) {
    unsigned u;
    asm("cvt.rna.tf32.f32 %0, %1;" : "=r"(u) : "f"(f));
    return u;
}

__device__ __forceinline__ void mma_tf32(float& d0, float& d1, float& d2, float& d3,
                                         unsigned a0, unsigned a1, unsigned a2, unsigned a3,
                                         unsigned b0, unsigned b1)
{
    asm volatile("mma.sync.aligned.m16n8k8.row.col.f32.tf32.tf32.f32 "
                 "{%0,%1,%2,%3}, {%4,%5,%6,%7}, {%8,%9}, {%0,%1,%2,%3};\n"
                 : "+f"(d0), "+f"(d1), "+f"(d2), "+f"(d3)
                 : "r"(a0), "r"(a1), "r"(a2), "r"(a3), "r"(b0), "r"(b1));
}

// ---------------- tf32 tensor-core GEMM: C = A @ W + bias ----------------
// A rows mapped: phys = (r/S_part)*in_sb + in_off + r%S_part (same for C with out_*)
#define GA_LD 36     // As row stride (floats)
#define GB_LD 136    // Bs row stride

__global__ __launch_bounds__(256) void gemm_tf32(
    const float* __restrict__ A, const float* __restrict__ W,
    const float* __restrict__ bias, float* __restrict__ C,
    int S_part, int in_sb, int in_off, int out_sb, int out_off)
{
    extern __shared__ float sm[];
    float* As = sm;                       // 2 x 128 x 36
    float* Bs = sm + 2 * 128 * GA_LD;     // 2 x 32 x 136

    const int t = threadIdx.x;
    const int lane = t & 31, w = t >> 5;
    const int g = lane >> 2, tig = lane & 3;
    const int wm = w >> 2, wn = w & 3;    // warp grid 2x4
    const int bm = blockIdx.y * 128;
    const int bn = blockIdx.x * 128;

    // A gmem: 4 float4 per thread per tile; row fixed per j
    const float* Aptr[4];
    #pragma unroll
    for (int j = 0; j < 4; j++) {
        int r = 32 * j + (t >> 3);
        int gr = bm + r;
        int ab = gr / S_part, as = gr - ab * S_part;
        Aptr[j] = A + (size_t)(ab * in_sb + in_off + as) * DIMN + ((t & 7) << 2);
    }
    // B gmem
    const float* Bptr[4];
    #pragma unroll
    for (int j = 0; j < 4; j++) {
        int r = 8 * j + (t >> 5);
        Bptr[j] = W + (size_t)r * DIMN + bn + ((t & 31) << 2);
    }

    // smem store offsets
    const int a_sr = (t >> 3);            // within 32-row group
    const int a_sc = (t & 7) << 2;
    const int b_sr = (t >> 5);
    const int b_sc = (t & 31) << 2;

    float acc[4][4][4];
    #pragma unroll
    for (int mt = 0; mt < 4; mt++)
        #pragma unroll
        for (int nt = 0; nt < 4; nt++)
            #pragma unroll
            for (int i = 0; i < 4; i++) acc[mt][nt][i] = 0.f;

    // stage k0 = 0 into buffer 0
    {
        #pragma unroll
        for (int j = 0; j < 4; j++) {
            float4 v = *(const float4*)(Aptr[j]);
            float* d = As + (32 * j + a_sr) * GA_LD + a_sc;
            d[0] = __uint_as_float(f2tf(v.x)); d[1] = __uint_as_float(f2tf(v.y));
            d[2] = __uint_as_float(f2tf(v.z)); d[3] = __uint_as_float(f2tf(v.w));
        }
        #pragma unroll
        for (int j = 0; j < 4; j++) {
            float4 v = *(const float4*)(Bptr[j]);
            float* d = Bs + (8 * j + b_sr) * GB_LD + b_sc;
            d[0] = __uint_as_float(f2tf(v.x)); d[1] = __uint_as_float(f2tf(v.y));
            d[2] = __uint_as_float(f2tf(v.z)); d[3] = __uint_as_float(f2tf(v.w));
        }
    }
    __syncthreads();

    const int NITER = DIMN / 32;          // 96
    for (int it = 0; it < NITER; it++) {
        int cur = it & 1;
        float4 apre[4], bpre[4];
        if (it + 1 < NITER) {
            int k0 = (it + 1) * 32;
            #pragma unroll
            for (int j = 0; j < 4; j++) apre[j] = *(const float4*)(Aptr[j] + k0);
            #pragma unroll
            for (int j = 0; j < 4; j++) bpre[j] = *(const float4*)(Bptr[j] + (size_t)k0 * DIMN);
        }

        const float* SA = As + cur * 128 * GA_LD + (wm * 64) * GA_LD;
        const float* SB = Bs + cur * 32 * GB_LD + wn * 32;
        #pragma unroll
        for (int ks = 0; ks < 4; ks++) {
            int kb = ks * 8;
            unsigned a[4][4];
            #pragma unroll
            for (int mt = 0; mt < 4; mt++) {
                const float* p = SA + (mt * 16 + g) * GA_LD + kb + tig;
                a[mt][0] = __float_as_uint(p[0]);
                a[mt][1] = __float_as_uint(p[8 * GA_LD]);
                a[mt][2] = __float_as_uint(p[4]);
                a[mt][3] = __float_as_uint(p[8 * GA_LD + 4]);
            }
            unsigned b[4][2];
            #pragma unroll
            for (int nt = 0; nt < 4; nt++) {
                const float* p = SB + (kb + tig) * GB_LD + nt * 8 + g;
                b[nt][0] = __float_as_uint(p[0]);
                b[nt][1] = __float_as_uint(p[4 * GB_LD]);
            }
            #pragma unroll
            for (int mt = 0; mt < 4; mt++)
                #pragma unroll
                for (int nt = 0; nt < 4; nt++)
                    mma_tf32(acc[mt][nt][0], acc[mt][nt][1], acc[mt][nt][2], acc[mt][nt][3],
                             a[mt][0], a[mt][1], a[mt][2], a[mt][3],
                             b[nt][0], b[nt][1]);
        }
        __syncthreads();
        if (it + 1 < NITER) {
            int nxt = cur ^ 1;
            #pragma unroll
            for (int j = 0; j < 4; j++) {
                float* d = As + nxt * 128 * GA_LD + (32 * j + a_sr) * GA_LD + a_sc;
                d[0] = __uint_as_float(f2tf(apre[j].x)); d[1] = __uint_as_float(f2tf(apre[j].y));
                d[2] = __uint_as_float(f2tf(apre[j].z)); d[3] = __uint_as_float(f2tf(apre[j].w));
            }
            #pragma unroll
            for (int j = 0; j < 4; j++) {
                float* d = Bs + nxt * 32 * GB_LD + (8 * j + b_sr) * GB_LD + b_sc;
                d[0] = __uint_as_float(f2tf(bpre[j].x)); d[1] = __uint_as_float(f2tf(bpre[j].y));
                d[2] = __uint_as_float(f2tf(bpre[j].z)); d[3] = __uint_as_float(f2tf(bpre[j].w));
            }
            __syncthreads();
        }
    }

    // epilogue
    #pragma unroll
    for (int mt = 0; mt < 4; mt++) {
        int r0 = bm + wm * 64 + mt * 16 + g;
        int r1 = r0 + 8;
        int cb0 = r0 / S_part, cs0 = r0 - cb0 * S_part;
        int cb1 = r1 / S_part, cs1 = r1 - cb1 * S_part;
        float* C0 = C + (size_t)(cb0 * out_sb + out_off + cs0) * DIMN;
        float* C1 = C + (size_t)(cb1 * out_sb + out_off + cs1) * DIMN;
        #pragma unroll
        for (int nt = 0; nt < 4; nt++) {
            int col = bn + wn * 32 + nt * 8 + 2 * tig;
            float bv0 = bias[col], bv1 = bias[col + 1];
            *(float2*)(C0 + col) = make_float2(acc[mt][nt][0] + bv0, acc[mt][nt][1] + bv1);
            *(float2*)(C1 + col) = make_float2(acc[mt][nt][2] + bv0, acc[mt][nt][3] + bv1);
        }
    }
}

// ---------------- per-head RMSNorm + RoPE ----------------
__global__ __launch_bounds__(128) void rmsrope_kernel(
    float* __restrict__ q, float* __restrict__ k,
    const float* __restrict__ cosb, const float* __restrict__ sinb,
    const float* __restrict__ gq, const float* __restrict__ gqc,
    const float* __restrict__ gk, const float* __restrict__ gkc)
{
    const int s = blockIdx.x;
    const int b = blockIdx.y;
    const int h = blockIdx.z % HEADS;
    const int which = blockIdx.z / HEADS;
    float* buf = which ? k : q;
    const float* g = which ? (s < S_TXT ? gkc : gk) : (s < S_TXT ? gqc : gq);
    const int d = threadIdx.x;

    const size_t base = ((size_t)(b * SEQ + s)) * DIMN + h * HD;
    float v = buf[base + d];
    float ss = v * v;
    #pragma unroll
    for (int o = 16; o; o >>= 1) ss += __shfl_xor_sync(0xffffffffu, ss, o);
    __shared__ float wsum[4];
    __shared__ float nbuf[HD];
    if ((d & 31) == 0) wsum[d >> 5] = ss;
    __syncthreads();
    float tot = wsum[0] + wsum[1] + wsum[2] + wsum[3];
    float r = rsqrtf(tot * (1.0f / HD) + 1e-6f);
    nbuf[d] = v * r * g[d];
    __syncthreads();
    if (d < 64) {
        float x1 = nbuf[2 * d], x2 = nbuf[2 * d + 1];
        float c = cosb[s * 64 + d], sn = sinb[s * 64 + d];
        buf[base + 2 * d]     = x1 * c - x2 * sn;
        buf[base + 2 * d + 1] = x1 * sn + x2 * c;
    }
}

// ---------------- flash attention (tf32 tensor cores) ----------------
#define QLD 132
#define KLD 132
#define VLD 136
#define PLD 68

__global__ __launch_bounds__(128) void attn_mma(
    const float* __restrict__ Q, const float* __restrict__ K,
    const float* __restrict__ V, float* __restrict__ O)
{
    extern __shared__ float sm[];
    float* Qs = sm;                       // 64 x 132
    float* Ks = Qs + 64 * QLD;            // 64 x 132  (row = key index, col = d)
    float* Vs = Ks + 64 * KLD;            // 64 x 136  (row = key index, col = d)
    float* Ps = Vs + 64 * VLD;            // 64 x 68

    const int t = threadIdx.x;
    const int lane = t & 31, w = t >> 5;
    const int g = lane >> 2, tig = lane & 3;
    const int mb = w * 16;                // warp's 16 q-rows within the 64-row tile
    const int m0 = blockIdx.x * 64;
    const int h = blockIdx.y;
    const int b = blockIdx.z;
    const size_t seqbase = (size_t)b * SEQ;

    // stage Q (scaled, tf32)
    const float* Qg = Q + (seqbase + m0) * DIMN + h * HD;
    for (int i = t; i < 2048; i += 128) {
        int r = i >> 5, c4 = (i & 31) << 2;
        float4 v = *(const float4*)(Qg + (size_t)r * DIMN + c4);
        float* d = Qs + r * QLD + c4;
        d[0] = __uint_as_float(f2tf(v.x * SCALE));
        d[1] = __uint_as_float(f2tf(v.y * SCALE));
        d[2] = __uint_as_float(f2tf(v.z * SCALE));
        d[3] = __uint_as_float(f2tf(v.w * SCALE));
    }

    float m0r = -1e30f, m1r = -1e30f, l0 = 0.f, l1 = 0.f;
    float o[16][4];
    #pragma unroll
    for (int nt = 0; nt < 16; nt++)
        #pragma unroll
        for (int i = 0; i < 4; i++) o[nt][i] = 0.f;

    for (int n0 = 0; n0 < SEQ; n0 += 64) {
        __syncthreads();   // previous iteration done with Ks/Vs
        const float* Kg = K + (seqbase + n0) * DIMN + h * HD;
        const float* Vg = V + (seqbase + n0) * DIMN + h * HD;
        for (int i = t; i < 2048; i += 128) {
            int r = i >> 5, c4 = (i & 31) << 2;
            float4 kv = *(const float4*)(Kg + (size_t)r * DIMN + c4);
            float4 vv = *(const float4*)(Vg + (size_t)r * DIMN + c4);
            float* dk = Ks + r * KLD + c4;
            dk[0] = __uint_as_float(f2tf(kv.x)); dk[1] = __uint_as_float(f2tf(kv.y));
            dk[2] = __uint_as_float(f2tf(kv.z)); dk[3] = __uint_as_float(f2tf(kv.w));
            float* dv = Vs + r * VLD + c4;
            dv[0] = __uint_as_float(f2tf(vv.x)); dv[1] = __uint_as_float(f2tf(vv.y));
            dv[2] = __uint_as_float(f2tf(vv.z)); dv[3] = __uint_as_float(f2tf(vv.w));
        }
        __syncthreads();

        // S = Q K^T  : warp computes 16x64
        float s[8][4];
        #pragma unroll
        for (int nt = 0; nt < 8; nt++)
            #pragma unroll
            for (int i = 0; i < 4; i++) s[nt][i] = 0.f;
        #pragma unroll
        for (int kk = 0; kk < 16; kk++) {
            int kb = kk * 8;
            const float* pa = Qs + (mb + g) * QLD + kb + tig;
            unsigned a0 = __float_as_uint(pa[0]);
            unsigned a1 = __float_as_uint(pa[8 * QLD]);
            unsigned a2 = __float_as_uint(pa[4]);
            unsigned a3 = __float_as_uint(pa[8 * QLD + 4]);
            #pragma unroll
            for (int nt = 0; nt < 8; nt++) {
                const float* pb = Ks + (nt * 8 + g) * KLD + kb + tig;
                unsigned b0 = __float_as_uint(pb[0]);
                unsigned b1 = __float_as_uint(pb[4]);
                mma_tf32(s[nt][0], s[nt][1], s[nt][2], s[nt][3], a0, a1, a2, a3, b0, b1);
            }
        }

        // online softmax in registers (rows g and g+8)
        float mx0 = -1e30f, mx1 = -1e30f;
        #pragma unroll
        for (int nt = 0; nt < 8; nt++) {
            mx0 = fmaxf(mx0, fmaxf(s[nt][0], s[nt][1]));
            mx1 = fmaxf(mx1, fmaxf(s[nt][2], s[nt][3]));
        }
        mx0 = fmaxf(mx0, __shfl_xor_sync(0xffffffffu, mx0, 1));
        mx0 = fmaxf(mx0, __shfl_xor_sync(0xffffffffu, mx0, 2));
        mx1 = fmaxf(mx1, __shfl_xor_sync(0xffffffffu, mx1, 1));
        mx1 = fmaxf(mx1, __shfl_xor_sync(0xffffffffu, mx1, 2));
        float mn0 = fmaxf(m0r, mx0), mn1 = fmaxf(m1r, mx1);
        float sc0 = __expf(m0r - mn0), sc1 = __expf(m1r - mn1);
        m0r = mn0; m1r = mn1;
        float sum0 = 0.f, sum1 = 0.f;
        #pragma unroll
        for (int nt = 0; nt < 8; nt++) {
            s[nt][0] = __expf(s[nt][0] - mn0); sum0 += s[nt][0];
            s[nt][1] = __expf(s[nt][1] - mn0); sum0 += s[nt][1];
            s[nt][2] = __expf(s[nt][2] - mn1); sum1 += s[nt][2];
            s[nt][3] = __expf(s[nt][3] - mn1); sum1 += s[nt][3];
        }
        sum0 += __shfl_xor_sync(0xffffffffu, sum0, 1);
        sum0 += __shfl_xor_sync(0xffffffffu, sum0, 2);
        sum1 += __shfl_xor_sync(0xffffffffu, sum1, 1);
        sum1 += __shfl_xor_sync(0xffffffffu, sum1, 2);
        l0 = l0 * sc0 + sum0;
        l1 = l1 * sc1 + sum1;

        // write P (warp-private rows; no block sync needed)
        #pragma unroll
        for (int nt = 0; nt < 8; nt++) {
            *(float2*)(Ps + (mb + g) * PLD + nt * 8 + 2 * tig)     = make_float2(s[nt][0], s[nt][1]);
            *(float2*)(Ps + (mb + g + 8) * PLD + nt * 8 + 2 * tig) = make_float2(s[nt][2], s[nt][3]);
        }

        // rescale O accumulators
        #pragma unroll
        for (int nt = 0; nt < 16; nt++) {
            o[nt][0] *= sc0; o[nt][1] *= sc0;
            o[nt][2] *= sc1; o[nt][3] *= sc1;
        }
        __syncwarp();

        // O += P @ V : warp computes 16x128
        #pragma unroll
        for (int kk = 0; kk < 8; kk++) {
            int kb = kk * 8;
            const float* pa = Ps + (mb + g) * PLD + kb + tig;
            unsigned a0 = __float_as_uint(pa[0]);
            unsigned a1 = __float_as_uint(pa[8 * PLD]);
            unsigned a2 = __float_as_uint(pa[4]);
            unsigned a3 = __float_as_uint(pa[8 * PLD + 4]);
            #pragma unroll
            for (int nt = 0; nt < 16; nt++) {
                const float* pb = Vs + (kb + tig) * VLD + nt * 8 + g;
                unsigned b0 = __float_as_uint(pb[0]);
                unsigned b1 = __float_as_uint(pb[4 * VLD]);
                mma_tf32(o[nt][0], o[nt][1], o[nt][2], o[nt][3], a0, a1, a2, a3, b0, b1);
            }
        }
    }

    // epilogue
    float inv0 = 1.f / l0, inv1 = 1.f / l1;
    float* Og = O + (seqbase + m0 + mb) * DIMN + h * HD;
    #pragma unroll
    for (int nt = 0; nt < 16; nt++) {
        int col = nt * 8 + 2 * tig;
        *(float2*)(Og + (size_t)g * DIMN + col) =
            make_float2(o[nt][0] * inv0, o[nt][1] * inv0);
        *(float2*)(Og + (size_t)(g + 8) * DIMN + col) =
            make_float2(o[nt][2] * inv1, o[nt][3] * inv1);
    }
}

// ---------------- launch ----------------
extern "C" void kernel_launch(void* const* d_in, const int* in_sizes, int n_in,
                              void* d_out, int out_size)
{
    const float* x        = (const float*)d_in[0];
    const float* ctx      = (const float*)d_in[1];
    const float* rope_cos = (const float*)d_in[2];
    const float* rope_sin = (const float*)d_in[3];
    const float* wq   = (const float*)d_in[4];
    const float* bq   = (const float*)d_in[5];
    const float* wk   = (const float*)d_in[6];
    const float* bk   = (const float*)d_in[7];
    const float* wv   = (const float*)d_in[8];
    const float* bv   = (const float*)d_in[9];
    const float* wqc  = (const float*)d_in[10];
    const float* bqc  = (const float*)d_in[11];
    const float* wkc  = (const float*)d_in[12];
    const float* bkc  = (const float*)d_in[13];
    const float* wvc  = (const float*)d_in[14];
    const float* bvc  = (const float*)d_in[15];
    const float* w_out     = (const float*)d_in[16];
    const float* b_out     = (const float*)d_in[17];
    const float* w_add_out = (const float*)d_in[18];
    const float* b_add_out = (const float*)d_in[19];
    const float* g_q  = (const float*)d_in[20];
    const float* g_k  = (const float*)d_in[21];
    const float* g_qc = (const float*)d_in[22];
    const float* g_kc = (const float*)d_in[23];
    float* out = (float*)d_out;

    float *qb, *kb, *vb, *ob;
    cudaGetSymbolAddress((void**)&qb, g_qbuf);
    cudaGetSymbolAddress((void**)&kb, g_kbuf);
    cudaGetSymbolAddress((void**)&vb, g_vbuf);
    cudaGetSymbolAddress((void**)&ob, g_obuf);

    const int smem_gemm = (2 * 128 * GA_LD + 2 * 32 * GB_LD) * 4;
    const int smem_attn = (64 * QLD + 64 * KLD + 64 * VLD + 64 * PLD) * 4;
    cudaFuncSetAttribute(gemm_tf32, cudaFuncAttributeMaxDynamicSharedMemorySize, smem_gemm);
    cudaFuncSetAttribute(attn_mma, cudaFuncAttributeMaxDynamicSharedMemorySize, smem_attn);

    dim3 blk(256);
    dim3 grid_ctx(DIMN / 128, (BATCH * S_TXT) / 128);
    dim3 grid_img(DIMN / 128, (BATCH * S_IMG) / 128);
    gemm_tf32<<<grid_ctx, blk, smem_gemm>>>(ctx, wqc, bqc, qb, S_TXT, S_TXT, 0, SEQ, 0);
    gemm_tf32<<<grid_ctx, blk, smem_gemm>>>(ctx, wkc, bkc, kb, S_TXT, S_TXT, 0, SEQ, 0);
    gemm_tf32<<<grid_ctx, blk, smem_gemm>>>(ctx, wvc, bvc, vb, S_TXT, S_TXT, 0, SEQ, 0);
    gemm_tf32<<<grid_img, blk, smem_gemm>>>(x, wq, bq, qb, S_IMG, S_IMG, 0, SEQ, S_TXT);
    gemm_tf32<<<grid_img, blk, smem_gemm>>>(x, wk, bk, kb, S_IMG, S_IMG, 0, SEQ, S_TXT);
    gemm_tf32<<<grid_img, blk, smem_gemm>>>(x, wv, bv, vb, S_IMG, S_IMG, 0, SEQ, S_TXT);

    dim3 grid_rr(SEQ, BATCH, 2 * HEADS);
    rmsrope_kernel<<<grid_rr, 128>>>(qb, kb, rope_cos, rope_sin, g_q, g_qc, g_k, g_kc);

    dim3 grid_at(SEQ / 64, HEADS, BATCH);
    attn_mma<<<grid_at, 128, smem_attn>>>(qb, kb, vb, ob);

    gemm_tf32<<<grid_ctx, blk, smem_gemm>>>(ob, w_add_out, b_add_out, out,
                                            S_TXT, SEQ, 0, S_TXT, 0);
    gemm_tf32<<<grid_img, blk, smem_gemm>>>(ob, w_out, b_out, out + (size_t)BATCH * S_TXT * DIMN,
                                            S_IMG, SEQ, S_TXT, S_IMG, 0);
}

// round 4
// speedup vs baseline: 4.6958x; 2.2977x over previous
#include <cuda_runtime.h>
#include <cuda_bf16.h>
#include <math.h>

#define DIMN 3072
#define HEADS 24
#define HD 128
#define BATCH 2
#define S_IMG 1024
#define S_TXT 512
#define SEQ 1536
#define SCALE 0.08838834764831845f   // 1/sqrt(128)

// ---------------- scratch ----------------
__device__ float g_qbuf[(size_t)BATCH * SEQ * DIMN];
__device__ float g_kbuf[(size_t)BATCH * SEQ * DIMN];
__device__ float g_vbuf[(size_t)BATCH * SEQ * DIMN];
__device__ float g_obuf[(size_t)BATCH * SEQ * DIMN];

__device__ __forceinline__ unsigned f2tf(float f) {
    unsigned u;
    asm("cvt.rna.tf32.f32 %0, %1;" : "=r"(u) : "f"(f));
    return u;
}

__device__ __forceinline__ void mma_tf32(float& d0, float& d1, float& d2, float& d3,
                                         unsigned a0, unsigned a1, unsigned a2, unsigned a3,
                                         unsigned b0, unsigned b1)
{
    asm volatile("mma.sync.aligned.m16n8k8.row.col.f32.tf32.tf32.f32 "
                 "{%0,%1,%2,%3}, {%4,%5,%6,%7}, {%8,%9}, {%0,%1,%2,%3};\n"
                 : "+f"(d0), "+f"(d1), "+f"(d2), "+f"(d3)
                 : "r"(a0), "r"(a1), "r"(a2), "r"(a3), "r"(b0), "r"(b1));
}

__device__ __forceinline__ unsigned s2u(const void* p) {
    unsigned r;
    asm("{.reg .u64 t; cvta.to.shared.u64 t, %1; cvt.u32.u64 %0, t;}" : "=r"(r) : "l"(p));
    return r;
}
__device__ __forceinline__ void cpa16(unsigned dst, const void* src) {
    asm volatile("cp.async.cg.shared.global [%0], [%1], 16;" :: "r"(dst), "l"(src));
}
__device__ __forceinline__ void cp_commit() {
    asm volatile("cp.async.commit_group;");
}
template <int N> __device__ __forceinline__ void cp_wait() {
    asm volatile("cp.async.wait_group %0;" :: "n"(N));
}

// ---------------- tf32 tensor-core GEMM: C = A @ W + bias ----------------
#define GA_LD 36
#define GB_LD 136
#define NSTAGE 3
#define ASTAGE (128 * GA_LD)
#define BSTAGE (32 * GB_LD)

__global__ __launch_bounds__(256) void gemm_tf32(
    const float* __restrict__ A,
    const float* __restrict__ W0, const float* __restrict__ W1, const float* __restrict__ W2,
    const float* __restrict__ b0_, const float* __restrict__ b1_, const float* __restrict__ b2_,
    float* __restrict__ C0, float* __restrict__ C1, float* __restrict__ C2,
    int S_part, int in_sb, int in_off, int out_sb, int out_off)
{
    extern __shared__ float sm[];
    float* As = sm;
    float* Bs = sm + NSTAGE * ASTAGE;

    const int z = blockIdx.z;
    const float* W    = (z == 0) ? W0 : (z == 1) ? W1 : W2;
    const float* bias = (z == 0) ? b0_ : (z == 1) ? b1_ : b2_;
    float* C          = (z == 0) ? C0 : (z == 1) ? C1 : C2;

    const int t = threadIdx.x;
    const int lane = t & 31, w = t >> 5;
    const int g = lane >> 2, tig = lane & 3;
    const int wm = w >> 2, wn = w & 3;
    const int bm = blockIdx.y * 128;
    const int bn = blockIdx.x * 128;

    const float* Aptr[4];
    #pragma unroll
    for (int j = 0; j < 4; j++) {
        int r = 32 * j + (t >> 3);
        int gr = bm + r;
        int ab = gr / S_part, as_ = gr - ab * S_part;
        Aptr[j] = A + (size_t)(ab * in_sb + in_off + as_) * DIMN + ((t & 7) << 2);
    }
    const float* Bptr[4];
    #pragma unroll
    for (int j = 0; j < 4; j++) {
        int r = 8 * j + (t >> 5);
        Bptr[j] = W + (size_t)r * DIMN + bn + ((t & 31) << 2);
    }

    const unsigned a_base = s2u(As);
    const unsigned b_base = s2u(Bs);
    unsigned a_off[4], b_off[4];
    #pragma unroll
    for (int j = 0; j < 4; j++) {
        a_off[j] = a_base + (unsigned)(((32 * j + (t >> 3)) * GA_LD + ((t & 7) << 2)) * 4);
        b_off[j] = b_base + (unsigned)(((8 * j + (t >> 5)) * GB_LD + ((t & 31) << 2)) * 4);
    }

    const int NITER = DIMN / 32;            // 96

    #pragma unroll
    for (int s = 0; s < 2; s++) {
        int k0 = s * 32;
        #pragma unroll
        for (int j = 0; j < 4; j++) cpa16(a_off[j] + s * ASTAGE * 4, Aptr[j] + k0);
        #pragma unroll
        for (int j = 0; j < 4; j++) cpa16(b_off[j] + s * BSTAGE * 4, Bptr[j] + (size_t)k0 * DIMN);
        cp_commit();
    }

    float acc[4][4][4];
    #pragma unroll
    for (int mt = 0; mt < 4; mt++)
        #pragma unroll
        for (int nt = 0; nt < 4; nt++)
            #pragma unroll
            for (int i = 0; i < 4; i++) acc[mt][nt][i] = 0.f;

    int st = 0;
    for (int it = 0; it < NITER; it++) {
        // RACE FIX: at the final iteration no group was committed after the
        // stage we are about to read, so wait_group<1> would leave THIS
        // stage's copy in flight. Drain fully there.
        if (it == NITER - 1) cp_wait<0>(); else cp_wait<1>();
        __syncthreads();

        const float* SA = As + st * ASTAGE + (wm * 64) * GA_LD;
        const float* SB = Bs + st * BSTAGE + wn * 32;
        #pragma unroll
        for (int ks = 0; ks < 4; ks++) {
            int kb = ks * 8;
            unsigned a[4][4];
            #pragma unroll
            for (int mt = 0; mt < 4; mt++) {
                const float* p = SA + (mt * 16 + g) * GA_LD + kb + tig;
                a[mt][0] = f2tf(p[0]);
                a[mt][1] = f2tf(p[8 * GA_LD]);
                a[mt][2] = f2tf(p[4]);
                a[mt][3] = f2tf(p[8 * GA_LD + 4]);
            }
            unsigned b[4][2];
            #pragma unroll
            for (int nt = 0; nt < 4; nt++) {
                const float* p = SB + (kb + tig) * GB_LD + nt * 8 + g;
                b[nt][0] = f2tf(p[0]);
                b[nt][1] = f2tf(p[4 * GB_LD]);
            }
            #pragma unroll
            for (int mt = 0; mt < 4; mt++)
                #pragma unroll
                for (int nt = 0; nt < 4; nt++)
                    mma_tf32(acc[mt][nt][0], acc[mt][nt][1], acc[mt][nt][2], acc[mt][nt][3],
                             a[mt][0], a[mt][1], a[mt][2], a[mt][3],
                             b[nt][0], b[nt][1]);
        }

        if (it + 2 < NITER) {
            int k0 = (it + 2) * 32;
            int ns = (st + 2) % NSTAGE;
            #pragma unroll
            for (int j = 0; j < 4; j++) cpa16(a_off[j] + ns * ASTAGE * 4, Aptr[j] + k0);
            #pragma unroll
            for (int j = 0; j < 4; j++) cpa16(b_off[j] + ns * BSTAGE * 4, Bptr[j] + (size_t)k0 * DIMN);
            cp_commit();
        }
        st = (st + 1) % NSTAGE;
    }

    #pragma unroll
    for (int mt = 0; mt < 4; mt++) {
        int r0 = bm + wm * 64 + mt * 16 + g;
        int r1 = r0 + 8;
        int cb0 = r0 / S_part, cs0 = r0 - cb0 * S_part;
        int cb1 = r1 / S_part, cs1 = r1 - cb1 * S_part;
        float* C0r = C + (size_t)(cb0 * out_sb + out_off + cs0) * DIMN;
        float* C1r = C + (size_t)(cb1 * out_sb + out_off + cs1) * DIMN;
        #pragma unroll
        for (int nt = 0; nt < 4; nt++) {
            int col = bn + wn * 32 + nt * 8 + 2 * tig;
            float bv0 = bias[col], bv1 = bias[col + 1];
            *(float2*)(C0r + col) = make_float2(acc[mt][nt][0] + bv0, acc[mt][nt][1] + bv1);
            *(float2*)(C1r + col) = make_float2(acc[mt][nt][2] + bv0, acc[mt][nt][3] + bv1);
        }
    }
}

// ---------------- per-head RMSNorm + RoPE ----------------
__global__ __launch_bounds__(128) void rmsrope_kernel(
    float* __restrict__ q, float* __restrict__ k,
    const float* __restrict__ cosb, const float* __restrict__ sinb,
    const float* __restrict__ gq, const float* __restrict__ gqc,
    const float* __restrict__ gk, const float* __restrict__ gkc)
{
    const int s = blockIdx.x;
    const int b = blockIdx.y;
    const int h = blockIdx.z % HEADS;
    const int which = blockIdx.z / HEADS;
    float* buf = which ? k : q;
    const float* g = which ? (s < S_TXT ? gkc : gk) : (s < S_TXT ? gqc : gq);
    const int d = threadIdx.x;

    const size_t base = ((size_t)(b * SEQ + s)) * DIMN + h * HD;
    float v = buf[base + d];
    float ss = v * v;
    #pragma unroll
    for (int o = 16; o; o >>= 1) ss += __shfl_xor_sync(0xffffffffu, ss, o);
    __shared__ float wsum[4];
    __shared__ float nbuf[HD];
    if ((d & 31) == 0) wsum[d >> 5] = ss;
    __syncthreads();
    float tot = wsum[0] + wsum[1] + wsum[2] + wsum[3];
    float r = rsqrtf(tot * (1.0f / HD) + 1e-6f);
    nbuf[d] = v * r * g[d];
    __syncthreads();
    if (d < 64) {
        float x1 = nbuf[2 * d], x2 = nbuf[2 * d + 1];
        float c = cosb[s * 64 + d], sn = sinb[s * 64 + d];
        buf[base + 2 * d]     = x1 * c - x2 * sn;
        buf[base + 2 * d + 1] = x1 * sn + x2 * c;
    }
}

// ---------------- flash attention (tf32 mma, 8 warps, cp.async K/V) ----------------
#define QLD 132
#define KLD 132
#define VLD 136
#define PLD 68

__global__ __launch_bounds__(256) void attn_mma(
    const float* __restrict__ Q, const float* __restrict__ K,
    const float* __restrict__ V, float* __restrict__ O)
{
    extern __shared__ float sm[];
    float* Qs = sm;                       // 128 x 132 (tf32, pre-scaled)
    float* Ks = Qs + 128 * QLD;           // 64 x 132
    float* Vs = Ks + 64 * KLD;            // 64 x 136
    float* Ps = Vs + 64 * VLD;            // 128 x 68

    const int t = threadIdx.x;
    const int lane = t & 31, w = t >> 5;
    const int g = lane >> 2, tig = lane & 3;
    const int mb = w * 16;
    const int m0 = blockIdx.x * 128;
    const int h = blockIdx.y;
    const int b = blockIdx.z;
    const size_t seqbase = (size_t)b * SEQ;

    const unsigned k_base = s2u(Ks);
    const unsigned v_base = s2u(Vs);

    const float* Qg = Q + (seqbase + m0) * DIMN + h * HD;
    for (int i = t; i < 128 * 32; i += 256) {
        int r = i >> 5, c4 = (i & 31) << 2;
        float4 v = *(const float4*)(Qg + (size_t)r * DIMN + c4);
        float* d = Qs + r * QLD + c4;
        d[0] = __uint_as_float(f2tf(v.x * SCALE));
        d[1] = __uint_as_float(f2tf(v.y * SCALE));
        d[2] = __uint_as_float(f2tf(v.z * SCALE));
        d[3] = __uint_as_float(f2tf(v.w * SCALE));
    }

    {
        const float* Kg = K + seqbase * DIMN + h * HD;
        const float* Vg = V + seqbase * DIMN + h * HD;
        #pragma unroll
        for (int j = 0; j < 8; j++) {
            int idx = j * 256 + t;
            int r = idx >> 5, c = (idx & 31) << 2;
            cpa16(k_base + (unsigned)((r * KLD + c) * 4), Kg + (size_t)r * DIMN + c);
        }
        cp_commit();
        #pragma unroll
        for (int j = 0; j < 8; j++) {
            int idx = j * 256 + t;
            int r = idx >> 5, c = (idx & 31) << 2;
            cpa16(v_base + (unsigned)((r * VLD + c) * 4), Vg + (size_t)r * DIMN + c);
        }
        cp_commit();
    }

    float m0r = -1e30f, m1r = -1e30f, l0 = 0.f, l1 = 0.f;
    float o[16][4];
    #pragma unroll
    for (int nt = 0; nt < 16; nt++)
        #pragma unroll
        for (int i = 0; i < 4; i++) o[nt][i] = 0.f;

    for (int n0 = 0; n0 < SEQ; n0 += 64) {
        const bool has_next = (n0 + 64 < SEQ);
        cp_wait<1>();          // newest group (V(n0) or later) may stay in flight; K(n0) done
        __syncthreads();

        // S = Q K^T (warp: 16x64)
        float s[8][4];
        #pragma unroll
        for (int nt = 0; nt < 8; nt++)
            #pragma unroll
            for (int i = 0; i < 4; i++) s[nt][i] = 0.f;
        #pragma unroll
        for (int kk = 0; kk < 16; kk++) {
            int kb = kk * 8;
            const float* pa = Qs + (mb + g) * QLD + kb + tig;
            unsigned a0 = __float_as_uint(pa[0]);
            unsigned a1 = __float_as_uint(pa[8 * QLD]);
            unsigned a2 = __float_as_uint(pa[4]);
            unsigned a3 = __float_as_uint(pa[8 * QLD + 4]);
            #pragma unroll
            for (int nt = 0; nt < 8; nt++) {
                const float* pb = Ks + (nt * 8 + g) * KLD + kb + tig;
                unsigned b0 = f2tf(pb[0]);
                unsigned b1 = f2tf(pb[4]);
                mma_tf32(s[nt][0], s[nt][1], s[nt][2], s[nt][3], a0, a1, a2, a3, b0, b1);
            }
        }
        __syncthreads();       // all warps done reading Ks

        if (has_next) {
            const float* Kg = K + (seqbase + n0 + 64) * DIMN + h * HD;
            #pragma unroll
            for (int j = 0; j < 8; j++) {
                int idx = j * 256 + t;
                int r = idx >> 5, c = (idx & 31) << 2;
                cpa16(k_base + (unsigned)((r * KLD + c) * 4), Kg + (size_t)r * DIMN + c);
            }
            cp_commit();
        }

        // online softmax (registers)
        float mx0 = -1e30f, mx1 = -1e30f;
        #pragma unroll
        for (int nt = 0; nt < 8; nt++) {
            mx0 = fmaxf(mx0, fmaxf(s[nt][0], s[nt][1]));
            mx1 = fmaxf(mx1, fmaxf(s[nt][2], s[nt][3]));
        }
        mx0 = fmaxf(mx0, __shfl_xor_sync(0xffffffffu, mx0, 1));
        mx0 = fmaxf(mx0, __shfl_xor_sync(0xffffffffu, mx0, 2));
        mx1 = fmaxf(mx1, __shfl_xor_sync(0xffffffffu, mx1, 1));
        mx1 = fmaxf(mx1, __shfl_xor_sync(0xffffffffu, mx1, 2));
        float mn0 = fmaxf(m0r, mx0), mn1 = fmaxf(m1r, mx1);
        float sc0 = __expf(m0r - mn0), sc1 = __expf(m1r - mn1);
        m0r = mn0; m1r = mn1;
        float sum0 = 0.f, sum1 = 0.f;
        #pragma unroll
        for (int nt = 0; nt < 8; nt++) {
            s[nt][0] = __expf(s[nt][0] - mn0); sum0 += s[nt][0];
            s[nt][1] = __expf(s[nt][1] - mn0); sum0 += s[nt][1];
            s[nt][2] = __expf(s[nt][2] - mn1); sum1 += s[nt][2];
            s[nt][3] = __expf(s[nt][3] - mn1); sum1 += s[nt][3];
        }
        sum0 += __shfl_xor_sync(0xffffffffu, sum0, 1);
        sum0 += __shfl_xor_sync(0xffffffffu, sum0, 2);
        sum1 += __shfl_xor_sync(0xffffffffu, sum1, 1);
        sum1 += __shfl_xor_sync(0xffffffffu, sum1, 2);
        l0 = l0 * sc0 + sum0;
        l1 = l1 * sc1 + sum1;

        #pragma unroll
        for (int nt = 0; nt < 8; nt++) {
            *(float2*)(Ps + (mb + g) * PLD + nt * 8 + 2 * tig) =
                make_float2(__uint_as_float(f2tf(s[nt][0])), __uint_as_float(f2tf(s[nt][1])));
            *(float2*)(Ps + (mb + g + 8) * PLD + nt * 8 + 2 * tig) =
                make_float2(__uint_as_float(f2tf(s[nt][2])), __uint_as_float(f2tf(s[nt][3])));
        }
        #pragma unroll
        for (int nt = 0; nt < 16; nt++) {
            o[nt][0] *= sc0; o[nt][1] *= sc0;
            o[nt][2] *= sc1; o[nt][3] *= sc1;
        }

        // RACE FIX: on the last tile no K-prefetch was committed above, so
        // wait<1> would leave V(last) — the tile PV reads — in flight.
        if (has_next) cp_wait<1>(); else cp_wait<0>();
        __syncthreads();

        // O += P @ V (warp: 16x128)
        #pragma unroll
        for (int kk = 0; kk < 8; kk++) {
            int kb = kk * 8;
            const float* pa = Ps + (mb + g) * PLD + kb + tig;
            unsigned a0 = __float_as_uint(pa[0]);
            unsigned a1 = __float_as_uint(pa[8 * PLD]);
            unsigned a2 = __float_as_uint(pa[4]);
            unsigned a3 = __float_as_uint(pa[8 * PLD + 4]);
            #pragma unroll
            for (int nt = 0; nt < 16; nt++) {
                const float* pb = Vs + (kb + tig) * VLD + nt * 8 + g;
                unsigned b0 = f2tf(pb[0]);
                unsigned b1 = f2tf(pb[4 * VLD]);
                mma_tf32(o[nt][0], o[nt][1], o[nt][2], o[nt][3], a0, a1, a2, a3, b0, b1);
            }
        }
        __syncthreads();       // all warps done reading Vs

        if (has_next) {
            const float* Vg = V + (seqbase + n0 + 64) * DIMN + h * HD;
            #pragma unroll
            for (int j = 0; j < 8; j++) {
                int idx = j * 256 + t;
                int r = idx >> 5, c = (idx & 31) << 2;
                cpa16(v_base + (unsigned)((r * VLD + c) * 4), Vg + (size_t)r * DIMN + c);
            }
            cp_commit();
        }
    }

    float inv0 = 1.f / l0, inv1 = 1.f / l1;
    float* Og = O + (seqbase + m0 + mb) * DIMN + h * HD;
    #pragma unroll
    for (int nt = 0; nt < 16; nt++) {
        int col = nt * 8 + 2 * tig;
        *(float2*)(Og + (size_t)g * DIMN + col) =
            make_float2(o[nt][0] * inv0, o[nt][1] * inv0);
        *(float2*)(Og + (size_t)(g + 8) * DIMN + col) =
            make_float2(o[nt][2] * inv1, o[nt][3] * inv1);
    }
}

// ---------------- launch ----------------
extern "C" void kernel_launch(void* const* d_in, const int* in_sizes, int n_in,
                              void* d_out, int out_size)
{
    const float* x        = (const float*)d_in[0];
    const float* ctx      = (const float*)d_in[1];
    const float* rope_cos = (const float*)d_in[2];
    const float* rope_sin = (const float*)d_in[3];
    const float* wq   = (const float*)d_in[4];
    const float* bq   = (const float*)d_in[5];
    const float* wk   = (const float*)d_in[6];
    const float* bk   = (const float*)d_in[7];
    const float* wv   = (const float*)d_in[8];
    const float* bv   = (const float*)d_in[9];
    const float* wqc  = (const float*)d_in[10];
    const float* bqc  = (const float*)d_in[11];
    const float* wkc  = (const float*)d_in[12];
    const float* bkc  = (const float*)d_in[13];
    const float* wvc  = (const float*)d_in[14];
    const float* bvc  = (const float*)d_in[15];
    const float* w_out     = (const float*)d_in[16];
    const float* b_out     = (const float*)d_in[17];
    const float* w_add_out = (const float*)d_in[18];
    const float* b_add_out = (const float*)d_in[19];
    const float* g_q  = (const float*)d_in[20];
    const float* g_k  = (const float*)d_in[21];
    const float* g_qc = (const float*)d_in[22];
    const float* g_kc = (const float*)d_in[23];
    float* out = (float*)d_out;

    float *qb, *kb, *vb, *ob;
    cudaGetSymbolAddress((void**)&qb, g_qbuf);
    cudaGetSymbolAddress((void**)&kb, g_kbuf);
    cudaGetSymbolAddress((void**)&vb, g_vbuf);
    cudaGetSymbolAddress((void**)&ob, g_obuf);

    const int smem_gemm = (NSTAGE * ASTAGE + NSTAGE * BSTAGE) * 4;
    const int smem_attn = (128 * QLD + 64 * KLD + 64 * VLD + 128 * PLD) * 4;
    cudaFuncSetAttribute(gemm_tf32, cudaFuncAttributeMaxDynamicSharedMemorySize, smem_gemm);
    cudaFuncSetAttribute(attn_mma, cudaFuncAttributeMaxDynamicSharedMemorySize, smem_attn);

    dim3 blk(256);
    dim3 grid_ctx3(DIMN / 128, (BATCH * S_TXT) / 128, 3);
    dim3 grid_img3(DIMN / 128, (BATCH * S_IMG) / 128, 3);
    gemm_tf32<<<grid_ctx3, blk, smem_gemm>>>(ctx, wqc, wkc, wvc, bqc, bkc, bvc,
                                             qb, kb, vb, S_TXT, S_TXT, 0, SEQ, 0);
    gemm_tf32<<<grid_img3, blk, smem_gemm>>>(x, wq, wk, wv, bq, bk, bv,
                                             qb, kb, vb, S_IMG, S_IMG, 0, SEQ, S_TXT);

    dim3 grid_rr(SEQ, BATCH, 2 * HEADS);
    rmsrope_kernel<<<grid_rr, 128>>>(qb, kb, rope_cos, rope_sin, g_q, g_qc, g_k, g_kc);

    dim3 grid_at(SEQ / 128, HEADS, BATCH);
    attn_mma<<<grid_at, blk, smem_attn>>>(qb, kb, vb, ob);

    dim3 grid_txt(DIMN / 128, (BATCH * S_TXT) / 128, 1);
    dim3 grid_img(DIMN / 128, (BATCH * S_IMG) / 128, 1);
    gemm_tf32<<<grid_txt, blk, smem_gemm>>>(ob, w_add_out, w_add_out, w_add_out,
                                            b_add_out, b_add_out, b_add_out,
                                            out, out, out, S_TXT, SEQ, 0, S_TXT, 0);
    gemm_tf32<<<grid_img, blk, smem_gemm>>>(ob, w_out, w_out, w_out,
                                            b_out, b_out, b_out,
                                            out + (size_t)BATCH * S_TXT * DIMN,
                                            out + (size_t)BATCH * S_TXT * DIMN,
                                            out + (size_t)BATCH * S_TXT * DIMN,
                                            S_IMG, SEQ, S_TXT, S_IMG, 0);
}